// round 7
// baseline (speedup 1.0000x reference)
#include <cuda_runtime.h>
#include <math.h>

#define SEQ   1024
#define BATCH 128
#define IND   300
#define HID   256
#define NCLS  5

// Scratch for x_proj: [SEQ, BATCH, HID] fp32 = 134 MB (device global; no allocs allowed)
__device__ float g_xp[(size_t)SEQ * BATCH * HID];

// ---- packed fp32x2 helpers (Blackwell FFMA2 via PTX; bit-level = 2 floats) ----
__device__ __forceinline__ void ffma2(unsigned long long& d,
                                      unsigned long long a,
                                      unsigned long long b) {
    asm("fma.rn.f32x2 %0, %1, %2, %0;" : "+l"(d) : "l"(a), "l"(b));
}
__device__ __forceinline__ unsigned long long addf2(unsigned long long a,
                                                    unsigned long long b) {
    unsigned long long r;
    asm("add.rn.f32x2 %0, %1, %2;" : "=l"(r) : "l"(a), "l"(b));
    return r;
}
__device__ __forceinline__ unsigned long long pack2(float x, float y) {
    unsigned long long r;
    asm("mov.b64 %0, {%1, %2};" : "=l"(r) : "f"(x), "f"(y));
    return r;
}
__device__ __forceinline__ float2 unpack2(unsigned long long v) {
    float2 r;
    asm("mov.b64 {%0, %1}, %2;" : "=f"(r.x), "=f"(r.y) : "l"(v));
    return r;
}
__device__ __forceinline__ unsigned long long d_as_ll(double v) {
    return __double_as_longlong(v);
}

// tanh(x) = 1 - 2/(1 + e^{2x}) via MUFU ex2/rcp. Correct limits:
// x->+inf: e=inf -> 1-0 = 1 ; x->-inf: e=0 -> 1-2 = -1. Abs err ~1e-6.
__device__ __forceinline__ float fast_tanh(float x) {
    float r;
    asm("{\n\t"
        ".reg .f32 e;\n\t"
        "mul.f32 e, %1, 0f4038AA3B;\n\t"   // 2*log2(e) = 2.8853902
        "ex2.approx.f32 e, e;\n\t"
        "add.f32 e, e, 0f3F800000;\n\t"
        "rcp.approx.f32 e, e;\n\t"
        "fma.rn.f32 %0, e, 0fC0000000, 0f3F800000;\n\t"
        "}" : "=f"(r) : "f"(x));
    return r;
}

// ---------------------------------------------------------------------------
// Kernel 1: x_proj[m, n] = inputs[m, :] . W_ih[n, :] + b_ih[n] + b_hh[n]
//   128x128x16 tile, 8x8 micro-tile, packed f32x2 FMAs.
//   Double-buffered smem (regs -> alternate buffer), ONE sync per k-tile:
//   next tile's global loads issue before compute and drain during it.
// ---------------------------------------------------------------------------
__global__ __launch_bounds__(256, 2) void gemm_xproj(
    const float* __restrict__ A,   // [131072, 300]
    const float* __restrict__ W,   // [256, 300]
    const float* __restrict__ bih,
    const float* __restrict__ bhh)
{
    const int K = IND;
    __shared__ __align__(16) float As[2][16][128];
    __shared__ __align__(16) float Bs[2][16][128];

    const int bm  = blockIdx.x * 128;
    const int bn  = blockIdx.y * 128;
    const int tid = threadIdx.x;
    const int trow = tid >> 4;        // 0..15
    const int tcol = tid & 15;        // 0..15

    unsigned long long acc2[8][4];
#pragma unroll
    for (int i = 0; i < 8; i++)
#pragma unroll
        for (int jj = 0; jj < 4; jj++) acc2[i][jj] = 0ull;

    const int l_r = tid >> 1;         // 0..127 (row within tile)
    const int l_c = (tid & 1) * 8;    // 0 or 8 (k offset within tile)

    const int ntiles = (K + 15) / 16; // 19
    float ra[8], rb[8];

    // Preload tile 0 -> regs -> smem buffer 0
#pragma unroll
    for (int i = 0; i < 8; i++) {
        int k = l_c + i;
        bool ok = (k < K);
        ra[i] = ok ? A[(size_t)(bm + l_r) * K + k] : 0.f;
        rb[i] = ok ? W[(size_t)(bn + l_r) * K + k] : 0.f;
    }
#pragma unroll
    for (int i = 0; i < 8; i++) {
        As[0][l_c + i][l_r] = ra[i];
        Bs[0][l_c + i][l_r] = rb[i];
    }
    __syncthreads();

    for (int t = 0; t < ntiles; t++) {
        const int buf = t & 1;

        // Issue next tile's global loads (latency covered by compute below)
        if (t + 1 < ntiles) {
            int k0 = (t + 1) * 16;
#pragma unroll
            for (int i = 0; i < 8; i++) {
                int k = k0 + l_c + i;
                bool ok = (k < K);
                ra[i] = ok ? A[(size_t)(bm + l_r) * K + k] : 0.f;
                rb[i] = ok ? W[(size_t)(bn + l_r) * K + k] : 0.f;
            }
        }

        // Compute on current buffer
#pragma unroll
        for (int kk = 0; kk < 16; kk++) {
            const float4*  As4 = reinterpret_cast<const float4*>(As[buf][kk]);
            const double2* Bs2 = reinterpret_cast<const double2*>(Bs[buf][kk]);
            float4 a01 = As4[trow * 2];
            float4 a23 = As4[trow * 2 + 1];
            float a[8] = {a01.x, a01.y, a01.z, a01.w, a23.x, a23.y, a23.z, a23.w};
            double2 bA = Bs2[tcol * 2];
            double2 bB = Bs2[tcol * 2 + 1];
            unsigned long long b2[4] = {d_as_ll(bA.x), d_as_ll(bA.y),
                                        d_as_ll(bB.x), d_as_ll(bB.y)};
#pragma unroll
            for (int i = 0; i < 8; i++) {
                unsigned long long ad = pack2(a[i], a[i]);
#pragma unroll
                for (int jj = 0; jj < 4; jj++) ffma2(acc2[i][jj], ad, b2[jj]);
            }
        }

        // Stage next tile into the other buffer (not read until after sync)
        if (t + 1 < ntiles) {
#pragma unroll
            for (int i = 0; i < 8; i++) {
                As[buf ^ 1][l_c + i][l_r] = ra[i];
                Bs[buf ^ 1][l_c + i][l_r] = rb[i];
            }
        }
        __syncthreads();
    }

    // Epilogue: add biases, store to g_xp
    float bias[8];
#pragma unroll
    for (int j = 0; j < 8; j++) {
        int n = bn + tcol * 8 + j;
        bias[j] = bih[n] + bhh[n];
    }
#pragma unroll
    for (int i = 0; i < 8; i++) {
        int m = bm + trow * 8 + i;
        float* dst = g_xp + (size_t)m * HID + bn + tcol * 8;
#pragma unroll
        for (int jj = 0; jj < 4; jj++) {
            float2 v = unpack2(acc2[i][jj]);
            dst[2 * jj]     = v.x + bias[2 * jj];
            dst[2 * jj + 1] = v.y + bias[2 * jj + 1];
        }
    }
}

// ---------------------------------------------------------------------------
// Kernel 2: per-batch RNN scan. One CTA per batch element, thread j owns
// hidden unit j. W_hh row j split: k=0..63 from smem, k=64..255 in 96 packed
// u64 registers. All FMAs packed f32x2 from double2 shared loads. Register
// portion runs FIRST (only h needed) so smem-W loads overlap FMA issue.
// Fast MUFU tanh. h double-buffered; one barrier per step.
// ---------------------------------------------------------------------------
#define SKV 64          // k-range served from shared memory
#define SK4 (SKV / 4)   // 16 double2 per hidden unit
#define RKV 192         // k-range held in registers (96 packed u64)

#define SCAN_SMEM_BYTES ((SK4 * 256 * 4 + 2 * HID + HID + 8) * (int)sizeof(float))

__global__ __launch_bounds__(256, 1) void rnn_scan(
    const float* __restrict__ Whh,   // [256,256] row-major
    const float* __restrict__ Wout,  // [5,256]
    const float* __restrict__ bout,  // [5]
    float* __restrict__ out)         // [128,5]
{
    extern __shared__ __align__(16) float sm[];
    double2* s_wd2 = reinterpret_cast<double2*>(sm);  // [SK4][256] double2
    float*   s_h   = sm + SK4 * 256 * 4;              // [2][256]
    float*   s_red = s_h + 2 * HID;                   // [256]
    float*   s_z   = s_red + HID;                     // [8]

    const int j = threadIdx.x;   // hidden unit
    const int b = blockIdx.x;    // batch element

    // Load shared W chunk: s_wd2[k4*256 + jj] = Whh[jj][4*k4 .. 4*k4+3]
    for (int idx = j; idx < SK4 * 256; idx += 256) {
        int k4 = idx >> 8;
        int jj = idx & 255;
        s_wd2[idx] = reinterpret_cast<const double2*>(Whh)[jj * (HID / 4) + k4];
    }

    // Register-resident W chunk: Whh[j][64..255] as 96 packed u64
    unsigned long long wreg[RKV / 2];
    {
        const double2* wrow =
            reinterpret_cast<const double2*>(Whh + (size_t)j * HID + SKV);
#pragma unroll
        for (int r = 0; r < RKV / 4; r++) {
            double2 v = wrow[r];
            wreg[2 * r]     = d_as_ll(v.x);
            wreg[2 * r + 1] = d_as_ll(v.y);
        }
    }

    s_h[j] = 0.f;
    s_h[HID + j] = 0.f;
    float hsum = 0.f;

    const float* xpb = g_xp + (size_t)b * HID + j;
    float xp_cur = xpb[0];
    __syncthreads();

    int buf = 0;
    for (int s = 0; s < SEQ; s++) {
        float xp_next = 0.f;
        if (s + 1 < SEQ) xp_next = xpb[(size_t)(s + 1) * (BATCH * HID)];

        const double2* h2 = reinterpret_cast<const double2*>(s_h + buf * HID);
        unsigned long long a0 = 0ull, a1 = 0ull, a2 = 0ull, a3 = 0ull;

        // Register-W portion first: only h broadcast loads on its input path
#pragma unroll
        for (int r = 0; r < RKV / 4; r++) {
            double2 hv = h2[SK4 + r];                  // broadcast
            ffma2(a2, wreg[2 * r],     d_as_ll(hv.x));
            ffma2(a3, wreg[2 * r + 1], d_as_ll(hv.y));
        }
        // Shared-W portion (W loads overlap the FMA stream above)
#pragma unroll
        for (int k4 = 0; k4 < SK4; k4++) {
            double2 wv = s_wd2[(k4 << 8) + j];
            double2 hv = h2[k4];                       // broadcast
            ffma2(a0, d_as_ll(wv.x), d_as_ll(hv.x));
            ffma2(a1, d_as_ll(wv.y), d_as_ll(hv.y));
        }

        float2 f = unpack2(addf2(addf2(a0, a1), addf2(a2, a3)));
        float hn = fast_tanh(xp_cur + f.x + f.y);
        hsum += hn;
        s_h[(buf ^ 1) * HID + j] = hn;
        xp_cur = xp_next;
        buf ^= 1;
        __syncthreads();
    }

    // Readout: out_sum[c] = sum_j Wout[c][j] * hsum[j] + SEQ * bout[c]
    s_red[j] = hsum;
    __syncthreads();

    if (j < NCLS * 32) {
        int c = j >> 5, lane = j & 31;
        float p = 0.f;
#pragma unroll
        for (int t = 0; t < HID / 32; t++)
            p += Wout[c * HID + lane + t * 32] * s_red[lane + t * 32];
#pragma unroll
        for (int off = 16; off > 0; off >>= 1)
            p += __shfl_down_sync(0xffffffffu, p, off);
        if (lane == 0) s_z[c] = p + (float)SEQ * bout[c];
    }
    __syncthreads();

    if (j < NCLS) {
        float z0 = s_z[0], z1 = s_z[1], z2 = s_z[2], z3 = s_z[3], z4 = s_z[4];
        float m = fmaxf(fmaxf(fmaxf(z0, z1), fmaxf(z2, z3)), z4);
        float lse = logf(expf(z0 - m) + expf(z1 - m) + expf(z2 - m) +
                         expf(z3 - m) + expf(z4 - m));
        out[b * NCLS + j] = s_z[j] - m - lse;
    }
}

// One-time, idempotent attribute setup (no device memory, no sync).
static int setup_attrs_once() {
    cudaFuncSetAttribute((const void*)rnn_scan,
                         cudaFuncAttributeMaxDynamicSharedMemorySize,
                         SCAN_SMEM_BYTES);
    return 0;
}

// ---------------------------------------------------------------------------
extern "C" void kernel_launch(void* const* d_in, const int* in_sizes, int n_in,
                              void* d_out, int out_size) {
    static int _attrs = setup_attrs_once();
    (void)_attrs;

    const float* inputs = (const float*)d_in[0];
    const float* W_ih   = (const float*)d_in[1];
    const float* W_hh   = (const float*)d_in[2];
    const float* b_ih   = (const float*)d_in[3];
    const float* b_hh   = (const float*)d_in[4];
    const float* W_out  = (const float*)d_in[5];
    const float* b_out  = (const float*)d_in[6];
    float* out = (float*)d_out;

    dim3 g1(1024, 2), t1(256);
    gemm_xproj<<<g1, t1>>>(inputs, W_ih, b_ih, b_hh);
    rnn_scan<<<BATCH, HID, SCAN_SMEM_BYTES>>>(W_hh, W_out, b_out, out);
}

// round 8
// speedup vs baseline: 1.0593x; 1.0593x over previous
#include <cuda_runtime.h>
#include <math.h>

#define SEQ   1024
#define BATCH 128
#define IND   300
#define HID   256
#define NCLS  5

// Scratch for x_proj: [SEQ, BATCH, HID] fp32 = 134 MB (device global; no allocs allowed)
__device__ float g_xp[(size_t)SEQ * BATCH * HID];

// ---- packed fp32x2 helpers (Blackwell FFMA2 via PTX; bit-level = 2 floats) ----
__device__ __forceinline__ void ffma2(unsigned long long& d,
                                      unsigned long long a,
                                      unsigned long long b) {
    asm("fma.rn.f32x2 %0, %1, %2, %0;" : "+l"(d) : "l"(a), "l"(b));
}
__device__ __forceinline__ unsigned long long addf2(unsigned long long a,
                                                    unsigned long long b) {
    unsigned long long r;
    asm("add.rn.f32x2 %0, %1, %2;" : "=l"(r) : "l"(a), "l"(b));
    return r;
}
__device__ __forceinline__ unsigned long long pack2(float x, float y) {
    unsigned long long r;
    asm("mov.b64 %0, {%1, %2};" : "=l"(r) : "f"(x), "f"(y));
    return r;
}
__device__ __forceinline__ float2 unpack2(unsigned long long v) {
    float2 r;
    asm("mov.b64 {%0, %1}, %2;" : "=f"(r.x), "=f"(r.y) : "l"(v));
    return r;
}
__device__ __forceinline__ unsigned long long d_as_ll(double v) {
    return __double_as_longlong(v);
}

// tanh(x) = 1 - 2/(1 + e^{2x}) via MUFU ex2/rcp. Correct limits at +/-inf.
__device__ __forceinline__ float fast_tanh(float x) {
    float r;
    asm("{\n\t"
        ".reg .f32 e;\n\t"
        "mul.f32 e, %1, 0f4038AA3B;\n\t"   // 2*log2(e)
        "ex2.approx.f32 e, e;\n\t"
        "add.f32 e, e, 0f3F800000;\n\t"
        "rcp.approx.f32 e, e;\n\t"
        "fma.rn.f32 %0, e, 0fC0000000, 0f3F800000;\n\t"
        "}" : "=f"(r) : "f"(x));
    return r;
}

// ---------------------------------------------------------------------------
// Kernel 1: x_proj GEMM (unchanged from R6: 128x128x16, f32x2, double-buffer)
// ---------------------------------------------------------------------------
__global__ __launch_bounds__(256, 2) void gemm_xproj(
    const float* __restrict__ A,   // [131072, 300]
    const float* __restrict__ W,   // [256, 300]
    const float* __restrict__ bih,
    const float* __restrict__ bhh)
{
    const int K = IND;
    __shared__ __align__(16) float As[2][16][128];
    __shared__ __align__(16) float Bs[2][16][128];

    const int bm  = blockIdx.x * 128;
    const int bn  = blockIdx.y * 128;
    const int tid = threadIdx.x;
    const int trow = tid >> 4;
    const int tcol = tid & 15;

    unsigned long long acc2[8][4];
#pragma unroll
    for (int i = 0; i < 8; i++)
#pragma unroll
        for (int jj = 0; jj < 4; jj++) acc2[i][jj] = 0ull;

    const int l_r = tid >> 1;
    const int l_c = (tid & 1) * 8;

    const int ntiles = (K + 15) / 16; // 19
    float ra[8], rb[8];

#pragma unroll
    for (int i = 0; i < 8; i++) {
        int k = l_c + i;
        bool ok = (k < K);
        ra[i] = ok ? A[(size_t)(bm + l_r) * K + k] : 0.f;
        rb[i] = ok ? W[(size_t)(bn + l_r) * K + k] : 0.f;
    }
#pragma unroll
    for (int i = 0; i < 8; i++) {
        As[0][l_c + i][l_r] = ra[i];
        Bs[0][l_c + i][l_r] = rb[i];
    }
    __syncthreads();

    for (int t = 0; t < ntiles; t++) {
        const int buf = t & 1;
        if (t + 1 < ntiles) {
            int k0 = (t + 1) * 16;
#pragma unroll
            for (int i = 0; i < 8; i++) {
                int k = k0 + l_c + i;
                bool ok = (k < K);
                ra[i] = ok ? A[(size_t)(bm + l_r) * K + k] : 0.f;
                rb[i] = ok ? W[(size_t)(bn + l_r) * K + k] : 0.f;
            }
        }
#pragma unroll
        for (int kk = 0; kk < 16; kk++) {
            const float4*  As4 = reinterpret_cast<const float4*>(As[buf][kk]);
            const double2* Bs2 = reinterpret_cast<const double2*>(Bs[buf][kk]);
            float4 a01 = As4[trow * 2];
            float4 a23 = As4[trow * 2 + 1];
            float a[8] = {a01.x, a01.y, a01.z, a01.w, a23.x, a23.y, a23.z, a23.w};
            double2 bA = Bs2[tcol * 2];
            double2 bB = Bs2[tcol * 2 + 1];
            unsigned long long b2[4] = {d_as_ll(bA.x), d_as_ll(bA.y),
                                        d_as_ll(bB.x), d_as_ll(bB.y)};
#pragma unroll
            for (int i = 0; i < 8; i++) {
                unsigned long long ad = pack2(a[i], a[i]);
#pragma unroll
                for (int jj = 0; jj < 4; jj++) ffma2(acc2[i][jj], ad, b2[jj]);
            }
        }
        if (t + 1 < ntiles) {
#pragma unroll
            for (int i = 0; i < 8; i++) {
                As[buf ^ 1][l_c + i][l_r] = ra[i];
                Bs[buf ^ 1][l_c + i][l_r] = rb[i];
            }
        }
        __syncthreads();
    }

    float bias[8];
#pragma unroll
    for (int j = 0; j < 8; j++) {
        int n = bn + tcol * 8 + j;
        bias[j] = bih[n] + bhh[n];
    }
#pragma unroll
    for (int i = 0; i < 8; i++) {
        int m = bm + trow * 8 + i;
        float* dst = g_xp + (size_t)m * HID + bn + tcol * 8;
#pragma unroll
        for (int jj = 0; jj < 4; jj++) {
            float2 v = unpack2(acc2[i][jj]);
            dst[2 * jj]     = v.x + bias[2 * jj];
            dst[2 * jj + 1] = v.y + bias[2 * jj + 1];
        }
    }
}

// ---------------------------------------------------------------------------
// Kernel 2: per-batch RNN scan, K-SPLIT over 512 threads (16 warps/SM).
// Thread (half, j): partial dot of W[j][half*128 .. half*128+127] with
// h[half*128 ..]. Per half: first 48 k-vals from smem, last 80 in 40 u64
// registers. Partials exchanged through smem; half 0 applies xp + tanh.
// Two light barriers per step. 4 warps/SMSP for latency hiding (was 2).
// ---------------------------------------------------------------------------
#define SW_K4 12     // double2 (16B / 4 floats) per half served from smem -> 48 floats
#define RW_U64 40    // packed u64 W regs per thread -> 80 floats

#define SCAN_SMEM_FLOATS (2 * SW_K4 * 256 * 4 + 2 * HID + HID + HID + 8)
#define SCAN_SMEM_BYTES  (SCAN_SMEM_FLOATS * (int)sizeof(float))

__global__ __launch_bounds__(512, 1) void rnn_scan(
    const float* __restrict__ Whh,   // [256,256] row-major
    const float* __restrict__ Wout,  // [5,256]
    const float* __restrict__ bout,  // [5]
    float* __restrict__ out)         // [128,5]
{
    extern __shared__ __align__(16) float sm[];
    double2* s_wd2 = reinterpret_cast<double2*>(sm);   // [2*SW_K4][256] double2
    float*   s_h   = sm + 2 * SW_K4 * 256 * 4;         // [2][256]
    float*   s_prt = s_h + 2 * HID;                    // [256] partials (half 1)
    float*   s_red = s_prt + HID;                      // [256]
    float*   s_z   = s_red + HID;                      // [8]

    const int tid  = threadIdx.x;
    const int j    = tid & 255;     // hidden unit
    const int half = tid >> 8;      // k-half (0 or 1)
    const int b    = blockIdx.x;    // batch element

    // smem W: s_wd2[(half*SW_K4 + k4)*256 + j] = Whh[j][half*128 + 4*k4 ..+3]
    const double2* W2 = reinterpret_cast<const double2*>(Whh);
    for (int idx = tid; idx < 2 * SW_K4 * 256; idx += 512) {
        int hlf = idx / (SW_K4 * 256);
        int rem = idx - hlf * (SW_K4 * 256);
        int k4  = rem >> 8;
        int jj  = rem & 255;
        s_wd2[idx] = W2[jj * (HID / 4) + hlf * 32 + k4];
    }

    // Register W: Whh[j][half*128 + 48 .. half*128 + 127] as 40 packed u64
    unsigned long long wreg[RW_U64];
    {
        const double2* wrow = reinterpret_cast<const double2*>(
            Whh + (size_t)j * HID + half * 128 + SW_K4 * 4);
#pragma unroll
        for (int r = 0; r < RW_U64 / 2; r++) {
            double2 v = wrow[r];
            wreg[2 * r]     = d_as_ll(v.x);
            wreg[2 * r + 1] = d_as_ll(v.y);
        }
    }

    if (tid < 2 * HID) s_h[tid] = 0.f;
    float hsum = 0.f;

    const float* xpb = g_xp + (size_t)b * HID + j;
    float xp_cur = (half == 0) ? xpb[0] : 0.f;
    __syncthreads();

    int buf = 0;
    for (int s = 0; s < SEQ; s++) {
        float xp_next = 0.f;
        if (half == 0 && s + 1 < SEQ)
            xp_next = xpb[(size_t)(s + 1) * (BATCH * HID)];

        // This thread's h-half as double2 (4 floats each)
        const double2* hh =
            reinterpret_cast<const double2*>(s_h + buf * HID) + half * 32;

        unsigned long long a0 = 0ull, a1 = 0ull, a2 = 0ull, a3 = 0ull;

        // Register-W portion (rel k4 = SW_K4 .. 31)
#pragma unroll
        for (int r = 0; r < RW_U64 / 2; r++) {
            double2 hv = hh[SW_K4 + r];                // broadcast
            ffma2(a2, wreg[2 * r],     d_as_ll(hv.x));
            ffma2(a3, wreg[2 * r + 1], d_as_ll(hv.y));
        }
        // smem-W portion (rel k4 = 0 .. SW_K4-1)
#pragma unroll
        for (int k4 = 0; k4 < SW_K4; k4++) {
            double2 wv = s_wd2[((half * SW_K4 + k4) << 8) + j];
            double2 hv = hh[k4];                       // broadcast
            ffma2(a0, d_as_ll(wv.x), d_as_ll(hv.x));
            ffma2(a1, d_as_ll(wv.y), d_as_ll(hv.y));
        }

        float2 f = unpack2(addf2(addf2(a0, a1), addf2(a2, a3)));
        float p = f.x + f.y;

        if (half == 1) s_prt[j] = p;
        __syncthreads();

        if (half == 0) {
            float hn = fast_tanh(xp_cur + p + s_prt[j]);
            hsum += hn;
            s_h[(buf ^ 1) * HID + j] = hn;
            xp_cur = xp_next;
        }
        buf ^= 1;
        __syncthreads();
    }

    // Readout: out_sum[c] = sum_j Wout[c][j] * hsum[j] + SEQ * bout[c]
    if (half == 0) s_red[j] = hsum;
    __syncthreads();

    if (tid < NCLS * 32) {
        int c = tid >> 5, lane = tid & 31;
        float p = 0.f;
#pragma unroll
        for (int t = 0; t < HID / 32; t++)
            p += Wout[c * HID + lane + t * 32] * s_red[lane + t * 32];
#pragma unroll
        for (int off = 16; off > 0; off >>= 1)
            p += __shfl_down_sync(0xffffffffu, p, off);
        if (lane == 0) s_z[c] = p + (float)SEQ * bout[c];
    }
    __syncthreads();

    if (tid < NCLS) {
        float z0 = s_z[0], z1 = s_z[1], z2 = s_z[2], z3 = s_z[3], z4 = s_z[4];
        float m = fmaxf(fmaxf(fmaxf(z0, z1), fmaxf(z2, z3)), z4);
        float lse = logf(expf(z0 - m) + expf(z1 - m) + expf(z2 - m) +
                         expf(z3 - m) + expf(z4 - m));
        out[b * NCLS + tid] = s_z[tid] - m - lse;
    }
}

// One-time, idempotent attribute setup (no device memory, no sync).
static int setup_attrs_once() {
    cudaFuncSetAttribute((const void*)rnn_scan,
                         cudaFuncAttributeMaxDynamicSharedMemorySize,
                         SCAN_SMEM_BYTES);
    return 0;
}

// ---------------------------------------------------------------------------
extern "C" void kernel_launch(void* const* d_in, const int* in_sizes, int n_in,
                              void* d_out, int out_size) {
    static int _attrs = setup_attrs_once();
    (void)_attrs;

    const float* inputs = (const float*)d_in[0];
    const float* W_ih   = (const float*)d_in[1];
    const float* W_hh   = (const float*)d_in[2];
    const float* b_ih   = (const float*)d_in[3];
    const float* b_hh   = (const float*)d_in[4];
    const float* W_out  = (const float*)d_in[5];
    const float* b_out  = (const float*)d_in[6];
    float* out = (float*)d_out;

    dim3 g1(1024, 2), t1(256);
    gemm_xproj<<<g1, t1>>>(inputs, W_ih, b_ih, b_hh);
    rnn_scan<<<BATCH, 512, SCAN_SMEM_BYTES>>>(W_hh, W_out, b_out, out);
}